// round 4
// baseline (speedup 1.0000x reference)
#include <cuda_runtime.h>
#include <cstdint>

// ---------------- problem constants ----------------
#define BB   2048      // batch
#define LL   64        // words / sentence
#define DD   300       // embedding dim (K of encoder GEMM)
#define CC   512       // conv out channels
#define HH   2048      // fc hidden
// encoder GEMM: M = BB*LL = 131072, N = CC = 512, K = 300 (padded to 320)
// fc1 GEMM:     M = BB = 2048,     N = HH = 2048, K = 2*CC = 1024

// ---------------- scratch (no allocations allowed) ----------------
__device__ float g_e[2 * BB * CC];      // e1 | e2   (8 MB)
__device__ float g_h[(size_t)BB * HH];  // tanh hidden (16 MB)

// ---------------- helpers ----------------
__device__ __forceinline__ uint32_t f2tf(float f) {
    uint32_t r;
    asm("cvt.rna.tf32.f32 %0, %1;" : "=r"(r) : "f"(f));
    return r;
}

__device__ __forceinline__ void mma_tf32(float c[4], const uint32_t a[4], const uint32_t b[2]) {
    asm volatile(
        "mma.sync.aligned.m16n8k8.row.col.f32.tf32.tf32.f32 "
        "{%0,%1,%2,%3}, {%4,%5,%6,%7}, {%8,%9}, {%0,%1,%2,%3};"
        : "+f"(c[0]), "+f"(c[1]), "+f"(c[2]), "+f"(c[3])
        : "r"(a[0]), "r"(a[1]), "r"(a[2]), "r"(a[3]), "r"(b[0]), "r"(b[1]));
}

#define KT  32      // K tile
#define PAD 36      // smem row stride (floats) — conflict-free fragment loads

// =====================================================================
// Kernel 1: encoder.  grid = (C/128, (B*L)/128, 2 inputs), block = 256
// Computes relu(x @ Wc^T + bc) and max over each sentence's 64 rows,
// writes g_e[z][b][c].
// =====================================================================
__global__ __launch_bounds__(256, 1)
void encode_kernel(const float* __restrict__ x1, const float* __restrict__ x2,
                   const float* __restrict__ Wc, const float* __restrict__ bc)
{
    __shared__ uint32_t As[128][PAD];
    __shared__ uint32_t Bs[128][PAD];
    __shared__ float    red[4][128];

    const float* __restrict__ x = (blockIdx.z == 0) ? x1 : x2;
    const int mbase = blockIdx.y * 128;   // row in flattened [B*L]
    const int nbase = blockIdx.x * 128;   // col in C

    const int tid  = threadIdx.x;
    const int warp = tid >> 5, lane = tid & 31;
    const int wm = warp & 3;              // 4 m-strips of 32 rows
    const int wn = warp >> 2;             // 2 n-strips of 64 cols
    const int g  = lane >> 2, tg = lane & 3;

    float acc[2][8][4] = {};

    for (int kb = 0; kb < 320; kb += KT) {
        // ---- cooperative load: 128 rows x 32 K, float4, tf32-rounded ----
        #pragma unroll
        for (int i = 0; i < 4; i++) {
            int slot = tid + i * 256;
            int row  = slot >> 3;
            int c4   = (slot & 7) * 4;
            int k    = kb + c4;
            float4 va = make_float4(0.f, 0.f, 0.f, 0.f);
            float4 vb = make_float4(0.f, 0.f, 0.f, 0.f);
            if (k < DD) {   // DD % 4 == 0, so a float4 is fully in or fully out
                va = *(const float4*)(x  + (size_t)(mbase + row) * DD + k);
                vb = *(const float4*)(Wc + (size_t)(nbase + row) * DD + k);
            }
            uint4 ta = make_uint4(f2tf(va.x), f2tf(va.y), f2tf(va.z), f2tf(va.w));
            uint4 tb = make_uint4(f2tf(vb.x), f2tf(vb.y), f2tf(vb.z), f2tf(vb.w));
            *(uint4*)&As[row][c4] = ta;
            *(uint4*)&Bs[row][c4] = tb;
        }
        __syncthreads();

        #pragma unroll
        for (int kk = 0; kk < KT; kk += 8) {
            uint32_t a[2][4], b[8][2];
            #pragma unroll
            for (int mi = 0; mi < 2; mi++) {
                int r = wm * 32 + mi * 16;
                a[mi][0] = As[r + g    ][kk + tg    ];
                a[mi][1] = As[r + g + 8][kk + tg    ];
                a[mi][2] = As[r + g    ][kk + tg + 4];
                a[mi][3] = As[r + g + 8][kk + tg + 4];
            }
            #pragma unroll
            for (int ni = 0; ni < 8; ni++) {
                int c = wn * 64 + ni * 8;
                b[ni][0] = Bs[c + g][kk + tg    ];
                b[ni][1] = Bs[c + g][kk + tg + 4];
            }
            #pragma unroll
            for (int mi = 0; mi < 2; mi++)
                #pragma unroll
                for (int ni = 0; ni < 8; ni++)
                    mma_tf32(acc[mi][ni], a[mi], b[ni]);
        }
        __syncthreads();
    }

    // ---- epilogue: raw max over the warp's 32 rows, per column slot ----
    // (relu(max+bc) == max(relu(.+bc)) since bias is per-column constant)
    #pragma unroll
    for (int ni = 0; ni < 8; ni++) {
        #pragma unroll
        for (int j = 0; j < 2; j++) {
            float m = fmaxf(fmaxf(acc[0][ni][j], acc[0][ni][j + 2]),
                            fmaxf(acc[1][ni][j], acc[1][ni][j + 2]));
            #pragma unroll
            for (int off = 4; off < 32; off <<= 1)
                m = fmaxf(m, __shfl_xor_sync(0xffffffffu, m, off));
            if (g == 0)
                red[wm][wn * 64 + ni * 8 + 2 * tg + j] = m;
        }
    }
    __syncthreads();

    // combine the two 32-row strips of each sentence, add bias, relu, store
    {
        int s = tid >> 7;        // sentence within tile (0..1)
        int c = tid & 127;       // column within tile
        float v = fmaxf(red[2 * s][c], red[2 * s + 1][c]);
        v = fmaxf(v + bc[nbase + c], 0.f);
        size_t b = (size_t)blockIdx.y * 2 + s;   // global sentence index
        g_e[((size_t)blockIdx.z * BB + b) * CC + nbase + c] = v;
    }
}

// =====================================================================
// Kernel 2: FC1.  grid = (H/128, B/128), block = 256
// feat = [e1-e2 | e1*e2] computed on the fly; h = tanh(feat@W1^T + b1)
// =====================================================================
__global__ __launch_bounds__(256, 1)
void fc1_kernel(const float* __restrict__ W1, const float* __restrict__ b1)
{
    __shared__ uint32_t As[128][PAD];
    __shared__ uint32_t Bs[128][PAD];

    const int mbase = blockIdx.y * 128;   // batch row
    const int nbase = blockIdx.x * 128;   // hidden col

    const int tid  = threadIdx.x;
    const int warp = tid >> 5, lane = tid & 31;
    const int wm = warp & 3, wn = warp >> 2;
    const int g  = lane >> 2, tg = lane & 3;

    const float* __restrict__ e1 = g_e;
    const float* __restrict__ e2 = g_e + (size_t)BB * CC;

    float acc[2][8][4] = {};

    for (int kb = 0; kb < 2 * CC; kb += KT) {
        #pragma unroll
        for (int i = 0; i < 4; i++) {
            int slot = tid + i * 256;
            int row  = slot >> 3;
            int c4   = (slot & 7) * 4;
            int j    = kb + c4;
            int brow = mbase + row;
            float4 v;
            if (j < CC) {
                float4 p = *(const float4*)(e1 + (size_t)brow * CC + j);
                float4 q = *(const float4*)(e2 + (size_t)brow * CC + j);
                v = make_float4(p.x - q.x, p.y - q.y, p.z - q.z, p.w - q.w);
            } else {
                int j2 = j - CC;
                float4 p = *(const float4*)(e1 + (size_t)brow * CC + j2);
                float4 q = *(const float4*)(e2 + (size_t)brow * CC + j2);
                v = make_float4(p.x * q.x, p.y * q.y, p.z * q.z, p.w * q.w);
            }
            float4 w = *(const float4*)(W1 + (size_t)(nbase + row) * (2 * CC) + j);
            *(uint4*)&As[row][c4] = make_uint4(f2tf(v.x), f2tf(v.y), f2tf(v.z), f2tf(v.w));
            *(uint4*)&Bs[row][c4] = make_uint4(f2tf(w.x), f2tf(w.y), f2tf(w.z), f2tf(w.w));
        }
        __syncthreads();

        #pragma unroll
        for (int kk = 0; kk < KT; kk += 8) {
            uint32_t a[2][4], b[8][2];
            #pragma unroll
            for (int mi = 0; mi < 2; mi++) {
                int r = wm * 32 + mi * 16;
                a[mi][0] = As[r + g    ][kk + tg    ];
                a[mi][1] = As[r + g + 8][kk + tg    ];
                a[mi][2] = As[r + g    ][kk + tg + 4];
                a[mi][3] = As[r + g + 8][kk + tg + 4];
            }
            #pragma unroll
            for (int ni = 0; ni < 8; ni++) {
                int c = wn * 64 + ni * 8;
                b[ni][0] = Bs[c + g][kk + tg    ];
                b[ni][1] = Bs[c + g][kk + tg + 4];
            }
            #pragma unroll
            for (int mi = 0; mi < 2; mi++)
                #pragma unroll
                for (int ni = 0; ni < 8; ni++)
                    mma_tf32(acc[mi][ni], a[mi], b[ni]);
        }
        __syncthreads();
    }

    // epilogue: bias + tanh, direct store
    #pragma unroll
    for (int mi = 0; mi < 2; mi++) {
        #pragma unroll
        for (int ni = 0; ni < 8; ni++) {
            #pragma unroll
            for (int q = 0; q < 4; q++) {
                int row = mbase + wm * 32 + mi * 16 + g + ((q >> 1) ? 8 : 0);
                int col = nbase + wn * 64 + ni * 8 + 2 * tg + (q & 1);
                g_h[(size_t)row * HH + col] = tanhf(acc[mi][ni][q] + b1[col]);
            }
        }
    }
}

// =====================================================================
// Kernel 3: FC2 (H -> 1), fp32.  grid = B, block = 256
// =====================================================================
__global__ __launch_bounds__(256)
void fc2_kernel(const float* __restrict__ W2, const float* __restrict__ b2,
                float* __restrict__ out)
{
    const int b = blockIdx.x;
    const float* __restrict__ h = g_h + (size_t)b * HH;
    float s = 0.f;
    for (int i = threadIdx.x; i < HH; i += 256)
        s += h[i] * W2[i];
    #pragma unroll
    for (int off = 16; off > 0; off >>= 1)
        s += __shfl_xor_sync(0xffffffffu, s, off);
    __shared__ float sm[8];
    int warp = threadIdx.x >> 5, lane = threadIdx.x & 31;
    if (lane == 0) sm[warp] = s;
    __syncthreads();
    if (warp == 0) {
        float v = (lane < 8) ? sm[lane] : 0.f;
        #pragma unroll
        for (int off = 4; off > 0; off >>= 1)
            v += __shfl_xor_sync(0xffffffffu, v, off);
        if (lane == 0) out[b] = v + b2[0];
    }
}

// =====================================================================
extern "C" void kernel_launch(void* const* d_in, const int* in_sizes, int n_in,
                              void* d_out, int out_size)
{
    (void)in_sizes; (void)n_in; (void)out_size;
    const float* x1 = (const float*)d_in[0];
    const float* x2 = (const float*)d_in[1];
    const float* Wc = (const float*)d_in[2];
    const float* bc = (const float*)d_in[3];
    const float* W1 = (const float*)d_in[4];
    const float* b1 = (const float*)d_in[5];
    const float* W2 = (const float*)d_in[6];
    const float* b2 = (const float*)d_in[7];
    float* out = (float*)d_out;

    dim3 g1(CC / 128, (BB * LL) / 128, 2);      // 4 x 1024 x 2
    encode_kernel<<<g1, 256>>>(x1, x2, Wc, bc);

    dim3 g2(HH / 128, BB / 128);                // 16 x 16
    fc1_kernel<<<g2, 256>>>(W1, b1);

    fc2_kernel<<<BB, 256>>>(W2, b2, out);
}

// round 5
// speedup vs baseline: 1.5255x; 1.5255x over previous
#include <cuda_runtime.h>
#include <cstdint>

// ---------------- problem constants ----------------
#define BB   2048      // batch
#define LL   64        // words / sentence
#define DD   300       // embedding dim (K of encoder GEMM)
#define CC   512       // conv out channels
#define HH   2048      // fc hidden
// encoder GEMM: M = BB*LL = 131072, N = CC = 512, K = 300 (padded to 320)
// fc1 GEMM:     M = BB = 2048,     N = HH = 2048, K = 2*CC = 1024

// ---------------- scratch (no allocations allowed) ----------------
__device__ float g_e[2 * BB * CC];            // e1 | e2        (8 MB)
__device__ float g_feat[(size_t)BB * 2 * CC]; // [e1-e2|e1*e2]  (8 MB)
__device__ float g_h[(size_t)BB * HH];        // tanh hidden    (16 MB)

// ---------------- helpers ----------------
__device__ __forceinline__ uint32_t f2tf(float f) {
    uint32_t r;
    asm("cvt.rna.tf32.f32 %0, %1;" : "=r"(r) : "f"(f));
    return r;
}

__device__ __forceinline__ void mma_tf32(float c[4], const uint32_t a[4], const uint32_t b[2]) {
    asm volatile(
        "mma.sync.aligned.m16n8k8.row.col.f32.tf32.tf32.f32 "
        "{%0,%1,%2,%3}, {%4,%5,%6,%7}, {%8,%9}, {%0,%1,%2,%3};"
        : "+f"(c[0]), "+f"(c[1]), "+f"(c[2]), "+f"(c[3])
        : "r"(a[0]), "r"(a[1]), "r"(a[2]), "r"(a[3]), "r"(b[0]), "r"(b[1]));
}

__device__ __forceinline__ void cpa16(uint32_t dst, const void* src, int sz) {
    asm volatile("cp.async.cg.shared.global [%0], [%1], 16, %2;"
                 :: "r"(dst), "l"(src), "r"(sz));
}
__device__ __forceinline__ void cpa_commit() {
    asm volatile("cp.async.commit_group;");
}

// ---------------- tiling ----------------
// CTA tile: 256 (M) x 128 (N), K-tile 32, 8 warps each owning a 64x64 subtile.
#define KT    32
#define PADW  36                     // smem row stride (words), 36 % 32 == 4
#define AW    (256 * PADW)           // words per A stage
#define BWW   (128 * PADW)           // words per B stage
#define SMEM_WORDS (2 * (AW + BWW))
#define SMEM_BYTES (SMEM_WORDS * 4)  // 110592

// =====================================================================
// Shared GEMM core pieces (used by both encode and fc1)
// =====================================================================
// A tile loader: 256 rows x 32 K (8 chunks of 4 floats per row)
__device__ __forceinline__ void load_A(uint32_t sbase, int buf,
                                       const float* __restrict__ A,
                                       int mbase, int kb, int lda, int kmax, int tid)
{
    #pragma unroll
    for (int it = 0; it < 8; it++) {
        int id  = tid + it * 256;
        int row = id >> 3;
        int ch  = id & 7;
        int k   = kb + ch * 4;
        const float* src = A + (size_t)(mbase + row) * lda + k;
        uint32_t dst = sbase + (uint32_t)(buf * AW + row * PADW + ch * 4) * 4u;
        cpa16(dst, src, (k < kmax) ? 16 : 0);
    }
}
// B tile loader: 128 rows x 32 K
__device__ __forceinline__ void load_B(uint32_t sbase, int buf,
                                       const float* __restrict__ B,
                                       int nbase, int kb, int ldb, int kmax, int tid)
{
    #pragma unroll
    for (int it = 0; it < 4; it++) {
        int id  = tid + it * 256;
        int row = id >> 3;
        int ch  = id & 7;
        int k   = kb + ch * 4;
        const float* src = B + (size_t)(nbase + row) * ldb + k;
        uint32_t dst = sbase + (uint32_t)(2 * AW + buf * BWW + row * PADW + ch * 4) * 4u;
        cpa16(dst, src, (k < kmax) ? 16 : 0);
    }
}

// per-warp compute on one staged K-tile; acc[4][8][4]
__device__ __forceinline__ void compute_tile(const uint32_t* __restrict__ sh, int buf,
                                             int wm, int wn, int g, int tg,
                                             float acc[4][8][4])
{
    const uint32_t* As = sh + buf * AW;
    const uint32_t* Bs = sh + 2 * AW + buf * BWW;
    #pragma unroll
    for (int kk = 0; kk < KT; kk += 8) {
        uint32_t a[4][4], b[8][2];
        #pragma unroll
        for (int f = 0; f < 4; f++) {
            int r = wm * 64 + f * 16;
            a[f][0] = f2tf(__uint_as_float(As[(r + g    ) * PADW + kk + tg    ]));
            a[f][1] = f2tf(__uint_as_float(As[(r + g + 8) * PADW + kk + tg    ]));
            a[f][2] = f2tf(__uint_as_float(As[(r + g    ) * PADW + kk + tg + 4]));
            a[f][3] = f2tf(__uint_as_float(As[(r + g + 8) * PADW + kk + tg + 4]));
        }
        #pragma unroll
        for (int ni = 0; ni < 8; ni++) {
            int c = wn * 64 + ni * 8;
            b[ni][0] = f2tf(__uint_as_float(Bs[(c + g) * PADW + kk + tg    ]));
            b[ni][1] = f2tf(__uint_as_float(Bs[(c + g) * PADW + kk + tg + 4]));
        }
        #pragma unroll
        for (int f = 0; f < 4; f++)
            #pragma unroll
            for (int ni = 0; ni < 8; ni++)
                mma_tf32(acc[f][ni], a[f], b[ni]);
    }
}

// =====================================================================
// Kernel 1: encoder.  grid = (C/128, (B*L)/256, 2), block = 256
// relu(max_L(x @ Wc^T) + bc) folded into epilogue; warp tile = 1 sentence.
// =====================================================================
__global__ __launch_bounds__(256, 1)
void encode_kernel(const float* __restrict__ x1, const float* __restrict__ x2,
                   const float* __restrict__ Wc, const float* __restrict__ bc)
{
    extern __shared__ uint32_t sh[];
    uint32_t sbase = (uint32_t)__cvta_generic_to_shared(sh);

    const float* __restrict__ x = (blockIdx.z == 0) ? x1 : x2;
    const int mbase = blockIdx.y * 256;
    const int nbase = blockIdx.x * 128;

    const int tid  = threadIdx.x;
    const int warp = tid >> 5, lane = tid & 31;
    const int wm = warp >> 1;      // 4 m-strips of 64 rows (one sentence each)
    const int wn = warp & 1;       // 2 n-strips of 64 cols
    const int g  = lane >> 2, tg = lane & 3;

    float acc[4][8][4] = {};

    const int NK = 320 / KT;       // 10
    load_A(sbase, 0, x,  mbase, 0, DD, DD, tid);
    load_B(sbase, 0, Wc, nbase, 0, DD, DD, tid);
    cpa_commit();

    for (int i = 0; i < NK; i++) {
        if (i + 1 < NK) {
            int kb = (i + 1) * KT;
            load_A(sbase, (i + 1) & 1, x,  mbase, kb, DD, DD, tid);
            load_B(sbase, (i + 1) & 1, Wc, nbase, kb, DD, DD, tid);
            cpa_commit();
            asm volatile("cp.async.wait_group 1;");
        } else {
            asm volatile("cp.async.wait_group 0;");
        }
        __syncthreads();
        compute_tile(sh, i & 1, wm, wn, g, tg, acc);
        __syncthreads();
    }

    // ---- epilogue: max over the warp's 64 rows (== one sentence) ----
    // relu(max + bc) == max(relu(.+bc)) since bias is per-column.
    const size_t sent = (size_t)blockIdx.y * 4 + wm;       // global sentence
    float* __restrict__ eout = g_e + ((size_t)blockIdx.z * BB + sent) * CC + nbase;

    #pragma unroll
    for (int ni = 0; ni < 8; ni++) {
        #pragma unroll
        for (int j = 0; j < 2; j++) {
            float m = -3.4e38f;
            #pragma unroll
            for (int f = 0; f < 4; f++)
                m = fmaxf(m, fmaxf(acc[f][ni][j], acc[f][ni][j + 2]));
            #pragma unroll
            for (int off = 4; off < 32; off <<= 1)
                m = fmaxf(m, __shfl_xor_sync(0xffffffffu, m, off));
            if (g == 0) {
                int col = wn * 64 + ni * 8 + 2 * tg + j;
                eout[col] = fmaxf(m + bc[nbase + col], 0.f);
            }
        }
    }
}

// =====================================================================
// Kernel 2: feat = [e1-e2 | e1*e2]  (elementwise, float4)
// =====================================================================
__global__ __launch_bounds__(256)
void feat_kernel()
{
    int idx = blockIdx.x * 256 + threadIdx.x;       // float4 index
    int row = idx >> 8;                              // 256 float4 per row of 1024
    int c4  = (idx & 255) * 4;
    const float* __restrict__ e1 = g_e;
    const float* __restrict__ e2 = g_e + (size_t)BB * CC;
    float4 v;
    if (c4 < CC) {
        float4 p = *(const float4*)(e1 + (size_t)row * CC + c4);
        float4 q = *(const float4*)(e2 + (size_t)row * CC + c4);
        v = make_float4(p.x - q.x, p.y - q.y, p.z - q.z, p.w - q.w);
    } else {
        int j = c4 - CC;
        float4 p = *(const float4*)(e1 + (size_t)row * CC + j);
        float4 q = *(const float4*)(e2 + (size_t)row * CC + j);
        v = make_float4(p.x * q.x, p.y * q.y, p.z * q.z, p.w * q.w);
    }
    *(float4*)(g_feat + (size_t)row * (2 * CC) + c4) = v;
}

// =====================================================================
// Kernel 3: FC1.  grid = (H/128, B/256), block = 256
// h = tanh(feat @ W1^T + b1)
// =====================================================================
__global__ __launch_bounds__(256, 1)
void fc1_kernel(const float* __restrict__ W1, const float* __restrict__ b1)
{
    extern __shared__ uint32_t sh[];
    uint32_t sbase = (uint32_t)__cvta_generic_to_shared(sh);

    const int mbase = blockIdx.y * 256;
    const int nbase = blockIdx.x * 128;

    const int tid  = threadIdx.x;
    const int warp = tid >> 5, lane = tid & 31;
    const int wm = warp >> 1, wn = warp & 1;
    const int g  = lane >> 2, tg = lane & 3;

    float acc[4][8][4] = {};

    const int NK = (2 * CC) / KT;   // 32
    load_A(sbase, 0, g_feat, mbase, 0, 2 * CC, 2 * CC, tid);
    load_B(sbase, 0, W1,     nbase, 0, 2 * CC, 2 * CC, tid);
    cpa_commit();

    for (int i = 0; i < NK; i++) {
        if (i + 1 < NK) {
            int kb = (i + 1) * KT;
            load_A(sbase, (i + 1) & 1, g_feat, mbase, kb, 2 * CC, 2 * CC, tid);
            load_B(sbase, (i + 1) & 1, W1,     nbase, kb, 2 * CC, 2 * CC, tid);
            cpa_commit();
            asm volatile("cp.async.wait_group 1;");
        } else {
            asm volatile("cp.async.wait_group 0;");
        }
        __syncthreads();
        compute_tile(sh, i & 1, wm, wn, g, tg, acc);
        __syncthreads();
    }

    // epilogue: bias + tanh, direct store
    #pragma unroll
    for (int f = 0; f < 4; f++) {
        #pragma unroll
        for (int ni = 0; ni < 8; ni++) {
            #pragma unroll
            for (int q = 0; q < 4; q++) {
                int row = mbase + wm * 64 + f * 16 + g + ((q >> 1) ? 8 : 0);
                int col = nbase + wn * 64 + ni * 8 + 2 * tg + (q & 1);
                g_h[(size_t)row * HH + col] = tanhf(acc[f][ni][q] + b1[col]);
            }
        }
    }
}

// =====================================================================
// Kernel 4: FC2 (H -> 1), fp32.  grid = B, block = 256
// =====================================================================
__global__ __launch_bounds__(256)
void fc2_kernel(const float* __restrict__ W2, const float* __restrict__ b2,
                float* __restrict__ out)
{
    const int b = blockIdx.x;
    const float* __restrict__ h = g_h + (size_t)b * HH;
    float s = 0.f;
    for (int i = threadIdx.x; i < HH; i += 256)
        s += h[i] * W2[i];
    #pragma unroll
    for (int off = 16; off > 0; off >>= 1)
        s += __shfl_xor_sync(0xffffffffu, s, off);
    __shared__ float sm[8];
    int warp = threadIdx.x >> 5, lane = threadIdx.x & 31;
    if (lane == 0) sm[warp] = s;
    __syncthreads();
    if (warp == 0) {
        float v = (lane < 8) ? sm[lane] : 0.f;
        #pragma unroll
        for (int off = 4; off > 0; off >>= 1)
            v += __shfl_xor_sync(0xffffffffu, v, off);
        if (lane == 0) out[b] = v + b2[0];
    }
}

// =====================================================================
extern "C" void kernel_launch(void* const* d_in, const int* in_sizes, int n_in,
                              void* d_out, int out_size)
{
    (void)in_sizes; (void)n_in; (void)out_size;
    const float* x1 = (const float*)d_in[0];
    const float* x2 = (const float*)d_in[1];
    const float* Wc = (const float*)d_in[2];
    const float* bc = (const float*)d_in[3];
    const float* W1 = (const float*)d_in[4];
    const float* b1 = (const float*)d_in[5];
    const float* W2 = (const float*)d_in[6];
    const float* b2 = (const float*)d_in[7];
    float* out = (float*)d_out;

    static bool attr_done = false;
    if (!attr_done) {
        cudaFuncSetAttribute(encode_kernel,
                             cudaFuncAttributeMaxDynamicSharedMemorySize, SMEM_BYTES);
        cudaFuncSetAttribute(fc1_kernel,
                             cudaFuncAttributeMaxDynamicSharedMemorySize, SMEM_BYTES);
        attr_done = true;
    }

    dim3 g1(CC / 128, (BB * LL) / 256, 2);        // 4 x 512 x 2 = 4096 CTAs
    encode_kernel<<<g1, 256, SMEM_BYTES>>>(x1, x2, Wc, bc);

    feat_kernel<<<(BB * 2 * CC) / 4 / 256, 256>>>();   // 4096 CTAs

    dim3 g2(HH / 128, BB / 256);                  // 16 x 8 = 128 CTAs
    fc1_kernel<<<g2, 256, SMEM_BYTES>>>(W1, b1);

    fc2_kernel<<<BB, 256>>>(W2, b2, out);
}

// round 7
// speedup vs baseline: 1.6449x; 1.0782x over previous
#include <cuda_runtime.h>
#include <cstdint>

// ---------------- problem constants ----------------
#define BB   2048      // batch
#define LL   64        // words / sentence
#define DD   300       // embedding dim (K of encoder GEMM)
#define CC   512       // conv out channels
#define HH   2048      // fc hidden
// encoder GEMM: M = BB*LL = 131072, N = CC = 512, K = 300
// fc1 GEMM:     M = BB = 2048,     N = HH = 2048, K = 2*CC = 1024

// ---------------- scratch (no allocations allowed) ----------------
__device__ float g_e[2 * BB * CC];      // e1 | e2   (8 MB)
__device__ float g_h[(size_t)BB * HH];  // tanh hidden (16 MB)

// ---------------- helpers ----------------
__device__ __forceinline__ uint32_t f2tf(float f) {
    uint32_t r;
    asm("cvt.rna.tf32.f32 %0, %1;" : "=r"(r) : "f"(f));
    return r;
}

__device__ __forceinline__ void mma_tf32(float c[4], const uint32_t a[4], const uint32_t b[2]) {
    asm volatile(
        "mma.sync.aligned.m16n8k8.row.col.f32.tf32.tf32.f32 "
        "{%0,%1,%2,%3}, {%4,%5,%6,%7}, {%8,%9}, {%0,%1,%2,%3};"
        : "+f"(c[0]), "+f"(c[1]), "+f"(c[2]), "+f"(c[3])
        : "r"(a[0]), "r"(a[1]), "r"(a[2]), "r"(a[3]), "r"(b[0]), "r"(b[1]));
}

// ---------------- tiling ----------------
// CTA tile: 256 (M) x 128 (N), K-tile 32, 8 warps each owning a 64x64 subtile.
#define KT    32
#define PADW  36                       // smem row stride (words)
#define AW    (256 * PADW)             // words per A stage
#define BWW   (128 * PADW)             // words per B stage
#define SMEM_WORDS (2 * (AW + BWW))
#define SMEM_BYTES (SMEM_WORDS * 4)    // 110592

// ---------------- STS of prefetched (tf32-rounded) tiles ----------------
__device__ __forceinline__ void sts_A(uint32_t* __restrict__ sh, int buf,
                                      const float4* __restrict__ ra, int tid)
{
    #pragma unroll
    for (int it = 0; it < 8; it++) {
        int id  = tid + it * 256;
        int row = id >> 3, ch = id & 7;
        uint32_t* d = sh + buf * AW + row * PADW + ch * 4;
        *(uint4*)d = make_uint4(f2tf(ra[it].x), f2tf(ra[it].y),
                                f2tf(ra[it].z), f2tf(ra[it].w));
    }
}
__device__ __forceinline__ void sts_B(uint32_t* __restrict__ sh, int buf,
                                      const float4* __restrict__ rb, int tid)
{
    #pragma unroll
    for (int it = 0; it < 4; it++) {
        int id  = tid + it * 256;
        int row = id >> 3, ch = id & 7;
        uint32_t* d = sh + 2 * AW + buf * BWW + row * PADW + ch * 4;
        *(uint4*)d = make_uint4(f2tf(rb[it].x), f2tf(rb[it].y),
                                f2tf(rb[it].z), f2tf(rb[it].w));
    }
}

// ---------------- per-warp compute on one staged K-tile ----------------
template <int NKS>
__device__ __forceinline__ void compute_tile(const uint32_t* __restrict__ sh, int buf,
                                             int wm, int wn, int g, int tg,
                                             float acc[4][8][4])
{
    const uint32_t* As = sh + buf * AW;
    const uint32_t* Bs = sh + 2 * AW + buf * BWW;
    #pragma unroll
    for (int kk = 0; kk < NKS * 8; kk += 8) {
        uint32_t a[4][4], b[8][2];
        #pragma unroll
        for (int f = 0; f < 4; f++) {
            int r = wm * 64 + f * 16;
            a[f][0] = As[(r + g    ) * PADW + kk + tg    ];
            a[f][1] = As[(r + g + 8) * PADW + kk + tg    ];
            a[f][2] = As[(r + g    ) * PADW + kk + tg + 4];
            a[f][3] = As[(r + g + 8) * PADW + kk + tg + 4];
        }
        #pragma unroll
        for (int ni = 0; ni < 8; ni++) {
            int c = wn * 64 + ni * 8;
            b[ni][0] = Bs[(c + g) * PADW + kk + tg    ];
            b[ni][1] = Bs[(c + g) * PADW + kk + tg + 4];
        }
        #pragma unroll
        for (int f = 0; f < 4; f++)
            #pragma unroll
            for (int ni = 0; ni < 8; ni++)
                mma_tf32(acc[f][ni], a[f], b[ni]);
    }
}

// =====================================================================
// Kernel 1: encoder.  grid = (C/128, (B*L)/256, 2), block = 256
// relu(max_L(x @ Wc^T) + bc) folded into epilogue; warp m-strip = 1 sentence.
// Pipeline: LDG tile i+1 -> regs, compute tile i, cvt+STS, one sync.
// =====================================================================
__global__ __launch_bounds__(256, 1)
void encode_kernel(const float* __restrict__ x1, const float* __restrict__ x2,
                   const float* __restrict__ Wc, const float* __restrict__ bc)
{
    extern __shared__ uint32_t sh[];

    const float* __restrict__ x = (blockIdx.z == 0) ? x1 : x2;
    const int mbase = blockIdx.y * 256;
    const int nbase = blockIdx.x * 128;

    const int tid  = threadIdx.x;
    const int warp = tid >> 5, lane = tid & 31;
    const int wm = warp >> 1;      // 4 m-strips of 64 rows (one sentence each)
    const int wn = warp & 1;       // 2 n-strips of 64 cols
    const int g  = lane >> 2, tg = lane & 3;

    // per-thread LDG coordinates
    const int arow = mbase + (tid >> 3);        // + it*32 rows
    const int brow = nbase + (tid >> 3);        // + it*16 rows (B covers 128 rows)
    const int kch  = (tid & 7) * 4;

    float acc[4][8][4] = {};
    float4 ra[8], rb[4];

    // ---- prologue: tile 0 ----
    {
        #pragma unroll
        for (int it = 0; it < 8; it++) {
            int k = kch;   // kb = 0
            ra[it] = (k < DD) ? *(const float4*)(x + (size_t)(arow + it * 32) * DD + k)
                              : make_float4(0.f, 0.f, 0.f, 0.f);
        }
        #pragma unroll
        for (int it = 0; it < 4; it++) {
            int k = kch;
            rb[it] = (k < DD) ? *(const float4*)(Wc + (size_t)(brow + it * 32) * DD + k)
                              : make_float4(0.f, 0.f, 0.f, 0.f);
        }
        sts_A(sh, 0, ra, tid);
        sts_B(sh, 0, rb, tid);
        __syncthreads();
    }

    const int NK = 10;     // K tiles of 32 (300 -> 320 padded; last tile trimmed)
    #pragma unroll 1
    for (int i = 0; i < NK - 1; i++) {
        // prefetch tile i+1
        const int kb = (i + 1) * KT;
        #pragma unroll
        for (int it = 0; it < 8; it++) {
            int k = kb + kch;
            ra[it] = (k < DD) ? *(const float4*)(x + (size_t)(arow + it * 32) * DD + k)
                              : make_float4(0.f, 0.f, 0.f, 0.f);
        }
        #pragma unroll
        for (int it = 0; it < 4; it++) {
            int k = kb + kch;
            rb[it] = (k < DD) ? *(const float4*)(Wc + (size_t)(brow + it * 32) * DD + k)
                              : make_float4(0.f, 0.f, 0.f, 0.f);
        }

        compute_tile<4>(sh, i & 1, wm, wn, g, tg, acc);

        sts_A(sh, (i + 1) & 1, ra, tid);
        sts_B(sh, (i + 1) & 1, rb, tid);
        __syncthreads();
    }
    // tail: tile 9 holds k=288..319, real data only to 300 -> 2 k-steps suffice
    compute_tile<2>(sh, (NK - 1) & 1, wm, wn, g, tg, acc);

    // ---- epilogue: max over the warp's 64 rows (== one sentence) ----
    // relu(max + bc) == max(relu(.+bc)) since bias is per-column.
    const size_t sent = (size_t)blockIdx.y * 4 + wm;       // global sentence
    float* __restrict__ eout = g_e + ((size_t)blockIdx.z * BB + sent) * CC + nbase;

    #pragma unroll
    for (int ni = 0; ni < 8; ni++) {
        #pragma unroll
        for (int j = 0; j < 2; j++) {
            float m = -3.4e38f;
            #pragma unroll
            for (int f = 0; f < 4; f++)
                m = fmaxf(m, fmaxf(acc[f][ni][j], acc[f][ni][j + 2]));
            #pragma unroll
            for (int off = 4; off < 32; off <<= 1)
                m = fmaxf(m, __shfl_xor_sync(0xffffffffu, m, off));
            if (g == 0) {
                int col = wn * 64 + ni * 8 + 2 * tg + j;
                eout[col] = fmaxf(m + bc[nbase + col], 0.f);
            }
        }
    }
}

// =====================================================================
// Kernel 2: FC1.  grid = (H/128, B/256), block = 256
// feat = [e1-e2 | e1*e2] computed on the fly in the A-tile prefetch.
// h = tanh(feat @ W1^T + b1)
// =====================================================================
__global__ __launch_bounds__(256, 1)
void fc1_kernel(const float* __restrict__ W1, const float* __restrict__ b1)
{
    extern __shared__ uint32_t sh[];

    const int mbase = blockIdx.y * 256;
    const int nbase = blockIdx.x * 128;

    const int tid  = threadIdx.x;
    const int warp = tid >> 5, lane = tid & 31;
    const int wm = warp >> 1, wn = warp & 1;
    const int g  = lane >> 2, tg = lane & 3;

    const float* __restrict__ e1 = g_e;
    const float* __restrict__ e2 = g_e + (size_t)BB * CC;

    const int arow = mbase + (tid >> 3);
    const int brow = nbase + (tid >> 3);
    const int kch  = (tid & 7) * 4;

    float acc[4][8][4] = {};
    float4 ra[8], rb[4];

    // feat A-chunk loader: j in [0,2C)
    auto load_feat = [&](int it, int j) -> float4 {
        int r = arow + it * 32;
        if (j < CC) {
            float4 p = *(const float4*)(e1 + (size_t)r * CC + j);
            float4 q = *(const float4*)(e2 + (size_t)r * CC + j);
            return make_float4(p.x - q.x, p.y - q.y, p.z - q.z, p.w - q.w);
        } else {
            int j2 = j - CC;
            float4 p = *(const float4*)(e1 + (size_t)r * CC + j2);
            float4 q = *(const float4*)(e2 + (size_t)r * CC + j2);
            return make_float4(p.x * q.x, p.y * q.y, p.z * q.z, p.w * q.w);
        }
    };

    // ---- prologue: tile 0 ----
    {
        #pragma unroll
        for (int it = 0; it < 8; it++) ra[it] = load_feat(it, kch);
        #pragma unroll
        for (int it = 0; it < 4; it++)
            rb[it] = *(const float4*)(W1 + (size_t)(brow + it * 32) * (2 * CC) + kch);
        sts_A(sh, 0, ra, tid);
        sts_B(sh, 0, rb, tid);
        __syncthreads();
    }

    const int NK = (2 * CC) / KT;   // 32
    #pragma unroll 1
    for (int i = 0; i < NK - 1; i++) {
        const int kb = (i + 1) * KT;
        #pragma unroll
        for (int it = 0; it < 8; it++) ra[it] = load_feat(it, kb + kch);
        #pragma unroll
        for (int it = 0; it < 4; it++)
            rb[it] = *(const float4*)(W1 + (size_t)(brow + it * 32) * (2 * CC) + kb + kch);

        compute_tile<4>(sh, i & 1, wm, wn, g, tg, acc);

        sts_A(sh, (i + 1) & 1, ra, tid);
        sts_B(sh, (i + 1) & 1, rb, tid);
        __syncthreads();
    }
    compute_tile<4>(sh, (NK - 1) & 1, wm, wn, g, tg, acc);

    // epilogue: bias + tanh, direct store
    #pragma unroll
    for (int f = 0; f < 4; f++) {
        #pragma unroll
        for (int ni = 0; ni < 8; ni++) {
            #pragma unroll
            for (int q = 0; q < 4; q++) {
                int row = mbase + wm * 64 + f * 16 + g + ((q >> 1) ? 8 : 0);
                int col = nbase + wn * 64 + ni * 8 + 2 * tg + (q & 1);
                g_h[(size_t)row * HH + col] = tanhf(acc[f][ni][q] + b1[col]);
            }
        }
    }
}

// =====================================================================
// Kernel 3: FC2 (H -> 1), fp32.  grid = B, block = 256
// =====================================================================
__global__ __launch_bounds__(256)
void fc2_kernel(const float* __restrict__ W2, const float* __restrict__ b2,
                float* __restrict__ out)
{
    const int b = blockIdx.x;
    const float* __restrict__ h = g_h + (size_t)b * HH;
    float s = 0.f;
    for (int i = threadIdx.x; i < HH; i += 256)
        s += h[i] * W2[i];
    #pragma unroll
    for (int off = 16; off > 0; off >>= 1)
        s += __shfl_xor_sync(0xffffffffu, s, off);
    __shared__ float sm[8];
    int warp = threadIdx.x >> 5, lane = threadIdx.x & 31;
    if (lane == 0) sm[warp] = s;
    __syncthreads();
    if (warp == 0) {
        float v = (lane < 8) ? sm[lane] : 0.f;
        #pragma unroll
        for (int off = 4; off > 0; off >>= 1)
            v += __shfl_xor_sync(0xffffffffu, v, off);
        if (lane == 0) out[b] = v + b2[0];
    }
}

// =====================================================================
extern "C" void kernel_launch(void* const* d_in, const int* in_sizes, int n_in,
                              void* d_out, int out_size)
{
    (void)in_sizes; (void)n_in; (void)out_size;
    const float* x1 = (const float*)d_in[0];
    const float* x2 = (const float*)d_in[1];
    const float* Wc = (const float*)d_in[2];
    const float* bc = (const float*)d_in[3];
    const float* W1 = (const float*)d_in[4];
    const float* b1 = (const float*)d_in[5];
    const float* W2 = (const float*)d_in[6];
    const float* b2 = (const float*)d_in[7];
    float* out = (float*)d_out;

    static bool attr_done = false;
    if (!attr_done) {
        cudaFuncSetAttribute(encode_kernel,
                             cudaFuncAttributeMaxDynamicSharedMemorySize, SMEM_BYTES);
        cudaFuncSetAttribute(fc1_kernel,
                             cudaFuncAttributeMaxDynamicSharedMemorySize, SMEM_BYTES);
        attr_done = true;
    }

    dim3 g1(CC / 128, (BB * LL) / 256, 2);        // 4 x 512 x 2 = 4096 CTAs
    encode_kernel<<<g1, 256, SMEM_BYTES>>>(x1, x2, Wc, bc);

    dim3 g2(HH / 128, BB / 256);                  // 16 x 8 = 128 CTAs
    fc1_kernel<<<g2, 256, SMEM_BYTES>>>(W1, b1);

    fc2_kernel<<<BB, 256>>>(W2, b2, out);
}